// round 4
// baseline (speedup 1.0000x reference)
#include <cuda_runtime.h>
#include <stdint.h>

// Problem constants
#define B_   64
#define N_   197
#define C_   768
#define H_   12
#define HD_  64
#define M_   (B_ * N_)     // 12608 rows
#define O3_  (3 * C_)      // 2304 qkv output dim

// Scratch (device globals: allocation-free rule)
__device__ float g_qkv[M_ * O3_];    // [12608, 2304]
__device__ float g_attn[M_ * C_];    // [12608, 768]

// ---------------------------------------------------------------------------
// helpers
// ---------------------------------------------------------------------------
__device__ __forceinline__ uint32_t f2tf(float x) {
    uint32_t r;
    asm("cvt.rna.tf32.f32 %0, %1;" : "=r"(r) : "f"(x));
    return r;
}

__device__ __forceinline__ void mma_m16n8k8(float c[4], const uint32_t a[4],
                                            uint32_t b0, uint32_t b1) {
    asm volatile(
        "mma.sync.aligned.m16n8k8.row.col.f32.tf32.tf32.f32 "
        "{%0,%1,%2,%3}, {%4,%5,%6,%7}, {%8,%9}, {%0,%1,%2,%3};"
        : "+f"(c[0]), "+f"(c[1]), "+f"(c[2]), "+f"(c[3])
        : "r"(a[0]), "r"(a[1]), "r"(a[2]), "r"(a[3]), "r"(b0), "r"(b1));
}

// ---------------------------------------------------------------------------
// TF32 GEMM: C[m][n] = sum_k A[m][k] * W[n][k]  (+ bias[n] + resid[m][n])
// A row-major [M,K], W row-major [N,K] (both k-contiguous -> row.col mma).
// CTA tile 128x128, BK=32, 256 threads (8 warps, 4x2), warp tile 32x64.
// ---------------------------------------------------------------------------
template <bool EPI>
__global__ void __launch_bounds__(256) gemm_tf32(
    const float* __restrict__ A, const float* __restrict__ W,
    float* __restrict__ C, int M, int N, int K,
    const float* __restrict__ bias, const float* __restrict__ resid)
{
    extern __shared__ uint32_t smem[];
    const int LDT = 36;              // 32 + 4 pad -> conflict-free frag loads
    const int TILE_W = 128 * LDT;    // 4608 words per buffer
    uint32_t* As = smem;             // [2][128][36]
    uint32_t* Bs = smem + 2 * TILE_W;

    const int tid  = threadIdx.x;
    const int m0   = blockIdx.y * 128;
    const int n0   = blockIdx.x * 128;
    const int warp = tid >> 5, lane = tid & 31;
    const int wm   = (warp & 3) * 32;
    const int wn   = (warp >> 2) * 64;
    const int gp   = lane >> 2, tg = lane & 3;

    float acc[2][8][4];
#pragma unroll
    for (int i = 0; i < 2; i++)
#pragma unroll
        for (int j = 0; j < 8; j++)
#pragma unroll
            for (int k = 0; k < 4; k++) acc[i][j][k] = 0.f;

    const int KT = K >> 5;
    float4 ra[4], rb[4];

    // ---- prologue: load tile kt=0, stage to buffer 0 ----
#pragma unroll
    for (int it = 0; it < 4; it++) {
        int f4 = it * 256 + tid;
        int row = f4 >> 3, c4 = (f4 & 7) << 2;
        int gr = m0 + row;
        ra[it] = (gr < M) ? *(const float4*)(A + (size_t)gr * K + c4)
                          : make_float4(0.f, 0.f, 0.f, 0.f);
        rb[it] = *(const float4*)(W + (size_t)(n0 + row) * K + c4);
    }
#pragma unroll
    for (int it = 0; it < 4; it++) {
        int f4 = it * 256 + tid;
        int row = f4 >> 3, c4 = (f4 & 7) << 2;
        uint4 ta = make_uint4(f2tf(ra[it].x), f2tf(ra[it].y), f2tf(ra[it].z), f2tf(ra[it].w));
        uint4 tb = make_uint4(f2tf(rb[it].x), f2tf(rb[it].y), f2tf(rb[it].z), f2tf(rb[it].w));
        *(uint4*)(As + row * LDT + c4) = ta;
        *(uint4*)(Bs + row * LDT + c4) = tb;
    }
    __syncthreads();

    for (int kt = 0; kt < KT; kt++) {
        if (kt + 1 < KT) {
            int kb = (kt + 1) << 5;
#pragma unroll
            for (int it = 0; it < 4; it++) {
                int f4 = it * 256 + tid;
                int row = f4 >> 3, c4 = (f4 & 7) << 2;
                int gr = m0 + row;
                ra[it] = (gr < M) ? *(const float4*)(A + (size_t)gr * K + kb + c4)
                                  : make_float4(0.f, 0.f, 0.f, 0.f);
                rb[it] = *(const float4*)(W + (size_t)(n0 + row) * K + kb + c4);
            }
        }
        const uint32_t* Ab = As + (kt & 1) * TILE_W;
        const uint32_t* Bb = Bs + (kt & 1) * TILE_W;
#pragma unroll
        for (int kk = 0; kk < 4; kk++) {
            int k8 = kk * 8;
            uint32_t af[2][4];
#pragma unroll
            for (int mt = 0; mt < 2; mt++) {
                const uint32_t* ap = Ab + (wm + mt * 16 + gp) * LDT + k8 + tg;
                af[mt][0] = ap[0];
                af[mt][2] = ap[4];
                af[mt][1] = ap[8 * LDT];
                af[mt][3] = ap[8 * LDT + 4];
            }
#pragma unroll
            for (int nt = 0; nt < 8; nt++) {
                const uint32_t* bp = Bb + (wn + nt * 8 + gp) * LDT + k8 + tg;
                uint32_t b0 = bp[0], b1 = bp[4];
                mma_m16n8k8(acc[0][nt], af[0], b0, b1);
                mma_m16n8k8(acc[1][nt], af[1], b0, b1);
            }
        }
        if (kt + 1 < KT) {
            uint32_t* Aw = As + ((kt + 1) & 1) * TILE_W;
            uint32_t* Bw = Bs + ((kt + 1) & 1) * TILE_W;
#pragma unroll
            for (int it = 0; it < 4; it++) {
                int f4 = it * 256 + tid;
                int row = f4 >> 3, c4 = (f4 & 7) << 2;
                uint4 ta = make_uint4(f2tf(ra[it].x), f2tf(ra[it].y), f2tf(ra[it].z), f2tf(ra[it].w));
                uint4 tb = make_uint4(f2tf(rb[it].x), f2tf(rb[it].y), f2tf(rb[it].z), f2tf(rb[it].w));
                *(uint4*)(Aw + row * LDT + c4) = ta;
                *(uint4*)(Bw + row * LDT + c4) = tb;
            }
        }
        __syncthreads();
    }

    // ---- epilogue ----
#pragma unroll
    for (int mt = 0; mt < 2; mt++) {
#pragma unroll
        for (int nt = 0; nt < 8; nt++) {
            int r0 = m0 + wm + mt * 16 + gp;
            int cc = n0 + wn + nt * 8 + tg * 2;
            if (r0 < M) {
                float2 v = make_float2(acc[mt][nt][0], acc[mt][nt][1]);
                if (EPI) {
                    v.x += bias[cc]     + resid[(size_t)r0 * N + cc];
                    v.y += bias[cc + 1] + resid[(size_t)r0 * N + cc + 1];
                }
                *(float2*)(C + (size_t)r0 * N + cc) = v;
            }
            if (r0 + 8 < M) {
                float2 v = make_float2(acc[mt][nt][2], acc[mt][nt][3]);
                if (EPI) {
                    v.x += bias[cc]     + resid[(size_t)(r0 + 8) * N + cc];
                    v.y += bias[cc + 1] + resid[(size_t)(r0 + 8) * N + cc + 1];
                }
                *(float2*)(C + (size_t)(r0 + 8) * N + cc) = v;
            }
        }
    }
}

// ---------------------------------------------------------------------------
// Fused attention: one CTA per (b, h, 64-query-row block). fp32 FFMA.
// S = (q*scale[h]) K^T  (diag masked), softmax, O = P V -> g_attn [m, h*64+d]
// smem: QT[64][68] (k-major), KT[64][256] (k-major, zero-padded cols),
//       S[64][260], V[197][68], inv[64]   ~198.6 KB
// ---------------------------------------------------------------------------
#define QT_LD 68
#define KT_LD 256
#define S_LD  260
#define V_LD  68
#define QT_OFF 0
#define KT_OFF (64 * QT_LD)                 // 4352
#define S_OFF  (KT_OFF + 64 * KT_LD)        // 20736
#define V_OFF  (S_OFF + 64 * S_LD)          // 37376
#define INV_OFF (V_OFF + 197 * V_LD)        // 50772
#define ATTN_SMEM_WORDS (INV_OFF + 64)      // 50836

__global__ void __launch_bounds__(256) attn_kernel(const float* __restrict__ scale)
{
    extern __shared__ float sm[];
    float* QT  = sm + QT_OFF;
    float* KT  = sm + KT_OFF;
    float* S   = sm + S_OFF;
    float* V   = sm + V_OFF;
    float* inv = sm + INV_OFF;

    const int tid = threadIdx.x;
    const int rb = blockIdx.x, h = blockIdx.y, b = blockIdx.z;
    const int base = b * N_;
    const int q0 = rb * 64;
    const int Nq = min(64, N_ - q0);
    const float sc = scale[h];

    // ---- stage Q (transposed, pre-scaled) ----
    for (int idx = tid; idx < 64 * 16; idx += 256) {
        int i = idx >> 4, d4 = (idx & 15) << 2;
        float4 v = make_float4(0.f, 0.f, 0.f, 0.f);
        if (i < Nq)
            v = *(const float4*)&g_qkv[(size_t)(base + q0 + i) * O3_ + h * HD_ + d4];
        QT[(d4 + 0) * QT_LD + i] = v.x * sc;
        QT[(d4 + 1) * QT_LD + i] = v.y * sc;
        QT[(d4 + 2) * QT_LD + i] = v.z * sc;
        QT[(d4 + 3) * QT_LD + i] = v.w * sc;
    }
    // ---- stage K (transposed, zero pad j>=197) ----
    for (int idx = tid; idx < 256 * 16; idx += 256) {
        int j = idx >> 4, d4 = (idx & 15) << 2;
        float4 v = make_float4(0.f, 0.f, 0.f, 0.f);
        if (j < N_)
            v = *(const float4*)&g_qkv[(size_t)(base + j) * O3_ + C_ + h * HD_ + d4];
        KT[(d4 + 0) * KT_LD + j] = v.x;
        KT[(d4 + 1) * KT_LD + j] = v.y;
        KT[(d4 + 2) * KT_LD + j] = v.z;
        KT[(d4 + 3) * KT_LD + j] = v.w;
    }
    // ---- stage V ----
    for (int idx = tid; idx < N_ * 16; idx += 256) {
        int j = idx >> 4, d4 = (idx & 15) << 2;
        float4 v = *(const float4*)&g_qkv[(size_t)(base + j) * O3_ + 2 * C_ + h * HD_ + d4];
        *(float4*)&V[j * V_LD + d4] = v;
    }
    __syncthreads();

    // ---- S = QK^T : 8 rows x 4 cols per thread, 2 column passes ----
    {
        const int ty = tid >> 5, tx = tid & 31;
        const int i0 = ty * 8;
#pragma unroll
        for (int pass = 0; pass < 2; pass++) {
            const int j0 = pass * 128 + tx * 4;
            float acc[8][4];
#pragma unroll
            for (int r = 0; r < 8; r++)
#pragma unroll
                for (int c = 0; c < 4; c++) acc[r][c] = 0.f;
#pragma unroll 8
            for (int k = 0; k < 64; k++) {
                float4 qa = *(const float4*)&QT[k * QT_LD + i0];
                float4 qb = *(const float4*)&QT[k * QT_LD + i0 + 4];
                float4 kv = *(const float4*)&KT[k * KT_LD + j0];
                float qr[8] = {qa.x, qa.y, qa.z, qa.w, qb.x, qb.y, qb.z, qb.w};
                float kc[4] = {kv.x, kv.y, kv.z, kv.w};
#pragma unroll
                for (int r = 0; r < 8; r++)
#pragma unroll
                    for (int c = 0; c < 4; c++)
                        acc[r][c] = fmaf(qr[r], kc[c], acc[r][c]);
            }
#pragma unroll
            for (int r = 0; r < 8; r++)
                *(float4*)&S[(i0 + r) * S_LD + j0] =
                    make_float4(acc[r][0], acc[r][1], acc[r][2], acc[r][3]);
        }
    }
    __syncthreads();

    // ---- diagonal self-mask ----
    {
        int row = tid >> 2;
        int gi = q0 + row;
        if ((tid & 3) == 0 && gi < N_) S[row * S_LD + gi] = -1e30f;
    }
    __syncthreads();

    // ---- softmax (4 threads per row), 1/sum deferred to PV epilogue ----
    {
        int row = tid >> 2, sub = tid & 3;
        float* Sr = &S[row * S_LD];
        float mx = -1e30f;
        for (int j = sub; j < N_; j += 4) mx = fmaxf(mx, Sr[j]);
        mx = fmaxf(mx, __shfl_xor_sync(0xffffffffu, mx, 1));
        mx = fmaxf(mx, __shfl_xor_sync(0xffffffffu, mx, 2));
        float s = 0.f;
        for (int j = sub; j < N_; j += 4) {
            float e = __expf(Sr[j] - mx);
            Sr[j] = e;
            s += e;
        }
        s += __shfl_xor_sync(0xffffffffu, s, 1);
        s += __shfl_xor_sync(0xffffffffu, s, 2);
        if (sub == 0) inv[row] = 1.0f / s;
    }
    __syncthreads();

    // ---- O = P V : 4x4 per thread ----
    {
        const int ty = tid >> 4, tx = tid & 15;
        const int i0 = ty * 4, d0 = tx * 4;
        float acc[4][4];
#pragma unroll
        for (int r = 0; r < 4; r++)
#pragma unroll
            for (int c = 0; c < 4; c++) acc[r][c] = 0.f;
#pragma unroll 4
        for (int j = 0; j < N_; j++) {
            float4 vv = *(const float4*)&V[j * V_LD + d0];
            float p0 = S[(i0 + 0) * S_LD + j];
            float p1 = S[(i0 + 1) * S_LD + j];
            float p2 = S[(i0 + 2) * S_LD + j];
            float p3 = S[(i0 + 3) * S_LD + j];
            float vc[4] = {vv.x, vv.y, vv.z, vv.w};
            float pr[4] = {p0, p1, p2, p3};
#pragma unroll
            for (int r = 0; r < 4; r++)
#pragma unroll
                for (int c = 0; c < 4; c++)
                    acc[r][c] = fmaf(pr[r], vc[c], acc[r][c]);
        }
#pragma unroll
        for (int r = 0; r < 4; r++) {
            if (i0 + r < Nq) {
                float iv = inv[i0 + r];
                float4 o = make_float4(acc[r][0] * iv, acc[r][1] * iv,
                                       acc[r][2] * iv, acc[r][3] * iv);
                *(float4*)&g_attn[(size_t)(base + q0 + i0 + r) * C_ + h * HD_ + d0] = o;
            }
        }
    }
}

// ---------------------------------------------------------------------------
// launch
// ---------------------------------------------------------------------------
extern "C" void kernel_launch(void* const* d_in, const int* in_sizes, int n_in,
                              void* d_out, int out_size)
{
    const float* x      = (const float*)d_in[0];
    const float* scale  = (const float*)d_in[1];
    const float* w_qkv  = (const float*)d_in[2];
    const float* w_proj = (const float*)d_in[3];
    const float* b_proj = (const float*)d_in[4];
    float* out = (float*)d_out;

    float *qkv_p, *attn_p;
    cudaGetSymbolAddress((void**)&qkv_p, g_qkv);
    cudaGetSymbolAddress((void**)&attn_p, g_attn);

    const int smem_gemm = 2 * 2 * 128 * 36 * 4;        // 73728 B
    const int smem_attn = ATTN_SMEM_WORDS * 4;         // 203344 B
    cudaFuncSetAttribute(gemm_tf32<false>, cudaFuncAttributeMaxDynamicSharedMemorySize, smem_gemm);
    cudaFuncSetAttribute(gemm_tf32<true>,  cudaFuncAttributeMaxDynamicSharedMemorySize, smem_gemm);
    cudaFuncSetAttribute(attn_kernel,      cudaFuncAttributeMaxDynamicSharedMemorySize, smem_attn);

    // 1) QKV projection: [12608, 2304]
    gemm_tf32<false><<<dim3(O3_ / 128, (M_ + 127) / 128), 256, smem_gemm>>>(
        x, w_qkv, qkv_p, M_, O3_, C_, nullptr, nullptr);

    // 2) fused masked attention per (row-block, head, batch)
    attn_kernel<<<dim3(4, H_, B_), 256, smem_attn>>>(scale);

    // 3) output projection + bias + residual
    gemm_tf32<true><<<dim3(C_ / 128, (M_ + 127) / 128), 256, smem_gemm>>>(
        attn_p, w_proj, out, M_, C_, C_, b_proj, x);
}

// round 7
// speedup vs baseline: 1.1657x; 1.1657x over previous
#include <cuda_runtime.h>
#include <stdint.h>

// Problem constants
#define B_   64
#define N_   197
#define C_   768
#define H_   12
#define HD_  64
#define M_   (B_ * N_)     // 12608 rows
#define O3_  (3 * C_)      // 2304 qkv output dim

// Scratch (device globals: allocation-free rule)
__device__ float g_qkv[M_ * O3_];    // [12608, 2304]
__device__ float g_attn[M_ * C_];    // [12608, 768]

// ---------------------------------------------------------------------------
// helpers
// ---------------------------------------------------------------------------
__device__ __forceinline__ void mma_m16n8k8(float c[4], const uint32_t a[4],
                                            uint32_t b0, uint32_t b1) {
    asm volatile(
        "mma.sync.aligned.m16n8k8.row.col.f32.tf32.tf32.f32 "
        "{%0,%1,%2,%3}, {%4,%5,%6,%7}, {%8,%9}, {%0,%1,%2,%3};"
        : "+f"(c[0]), "+f"(c[1]), "+f"(c[2]), "+f"(c[3])
        : "r"(a[0]), "r"(a[1]), "r"(a[2]), "r"(a[3]), "r"(b0), "r"(b1));
}

__device__ __forceinline__ void cp_async16(uint32_t s, const void* g, int srcsz) {
    asm volatile("cp.async.cg.shared.global [%0], [%1], 16, %2;"
                 :: "r"(s), "l"(g), "r"(srcsz));
}
#define CP_COMMIT() asm volatile("cp.async.commit_group;")

// ---------------------------------------------------------------------------
// TF32 GEMM: C[m][n] = sum_k A[m][k] * W[n][k]  (+ bias[n] + resid[m][n])
// A row-major [M,K], W row-major [N,K]. CTA tile 128x128, BK=32, 256 threads.
// cp.async double-buffered staging; fp32 bits fed to tf32 mma (HW truncation).
// ---------------------------------------------------------------------------
template <bool EPI>
__global__ void __launch_bounds__(256) gemm_tf32(
    const float* __restrict__ A, const float* __restrict__ W,
    float* __restrict__ C, int M, int N, int K,
    const float* __restrict__ bias, const float* __restrict__ resid)
{
    extern __shared__ float smem[];
    const int LDT = 36;              // 32 + 4 pad -> conflict-free frag loads
    const int TILE_W = 128 * LDT;    // words per buffer

    const int tid  = threadIdx.x;
    const int m0   = blockIdx.y * 128;
    const int n0   = blockIdx.x * 128;
    const int warp = tid >> 5, lane = tid & 31;
    const int wm   = (warp & 3) * 32;
    const int wn   = (warp >> 2) * 64;
    const int gp   = lane >> 2, tg = lane & 3;

    const uint32_t smem_u32 = (uint32_t)__cvta_generic_to_shared(smem);

    // per-thread staging descriptors (4 float4 per matrix per tile)
    const float* Ag[4];
    const float* Wg[4];
    int          av[4];
    uint32_t     sa[4], sb[4];
#pragma unroll
    for (int it = 0; it < 4; it++) {
        int f4 = it * 256 + tid;
        int row = f4 >> 3, c4 = (f4 & 7) << 2;
        int gra = m0 + row;
        av[it] = (gra < M) ? 16 : 0;
        Ag[it] = A + (size_t)(gra < M ? gra : 0) * K + c4;
        Wg[it] = W + (size_t)(n0 + row) * K + c4;
        sa[it] = smem_u32 + (uint32_t)(row * LDT + c4) * 4u;
        sb[it] = smem_u32 + (uint32_t)(2 * TILE_W + row * LDT + c4) * 4u;
    }

    float acc[2][8][4];
#pragma unroll
    for (int i = 0; i < 2; i++)
#pragma unroll
        for (int j = 0; j < 8; j++)
#pragma unroll
            for (int k = 0; k < 4; k++) acc[i][j][k] = 0.f;

    const int KT = K >> 5;

    // prologue: tile 0 -> buffer 0
#pragma unroll
    for (int it = 0; it < 4; it++) {
        cp_async16(sa[it], Ag[it], av[it]);
        cp_async16(sb[it], Wg[it], 16);
    }
    CP_COMMIT();

    for (int kt = 0; kt < KT; kt++) {
        if (kt + 1 < KT) {
            int kb = (kt + 1) << 5;
            uint32_t boff = (uint32_t)(((kt + 1) & 1) * TILE_W) * 4u;
#pragma unroll
            for (int it = 0; it < 4; it++) {
                cp_async16(sa[it] + boff, Ag[it] + kb, av[it]);
                cp_async16(sb[it] + boff, Wg[it] + kb, 16);
            }
            CP_COMMIT();
            asm volatile("cp.async.wait_group 1;");
        } else {
            asm volatile("cp.async.wait_group 0;");
        }
        __syncthreads();

        const uint32_t* Ab = (const uint32_t*)smem + (kt & 1) * TILE_W;
        const uint32_t* Bb = (const uint32_t*)smem + 2 * TILE_W + (kt & 1) * TILE_W;
#pragma unroll
        for (int kk = 0; kk < 4; kk++) {
            int k8 = kk * 8;
            uint32_t af[2][4];
#pragma unroll
            for (int mt = 0; mt < 2; mt++) {
                const uint32_t* ap = Ab + (wm + mt * 16 + gp) * LDT + k8 + tg;
                af[mt][0] = ap[0];
                af[mt][2] = ap[4];
                af[mt][1] = ap[8 * LDT];
                af[mt][3] = ap[8 * LDT + 4];
            }
#pragma unroll
            for (int nt = 0; nt < 8; nt++) {
                const uint32_t* bp = Bb + (wn + nt * 8 + gp) * LDT + k8 + tg;
                uint32_t b0 = bp[0], b1 = bp[4];
                mma_m16n8k8(acc[0][nt], af[0], b0, b1);
                mma_m16n8k8(acc[1][nt], af[1], b0, b1);
            }
        }
        __syncthreads();
    }

    // ---- epilogue ----
#pragma unroll
    for (int mt = 0; mt < 2; mt++) {
#pragma unroll
        for (int nt = 0; nt < 8; nt++) {
            int r0 = m0 + wm + mt * 16 + gp;
            int cc = n0 + wn + nt * 8 + tg * 2;
            if (r0 < M) {
                float2 v = make_float2(acc[mt][nt][0], acc[mt][nt][1]);
                if (EPI) {
                    v.x += bias[cc]     + resid[(size_t)r0 * N + cc];
                    v.y += bias[cc + 1] + resid[(size_t)r0 * N + cc + 1];
                }
                *(float2*)(C + (size_t)r0 * N + cc) = v;
            }
            if (r0 + 8 < M) {
                float2 v = make_float2(acc[mt][nt][2], acc[mt][nt][3]);
                if (EPI) {
                    v.x += bias[cc]     + resid[(size_t)(r0 + 8) * N + cc];
                    v.y += bias[cc + 1] + resid[(size_t)(r0 + 8) * N + cc + 1];
                }
                *(float2*)(C + (size_t)(r0 + 8) * N + cc) = v;
            }
        }
    }
}

// ---------------------------------------------------------------------------
// Fused attention with tf32 MMA. One CTA per (b, h, 64-query block).
// S = (Q*scale) K^T (diag-masked softmax), O = P V.  K/V padded to 208 rows.
//   Q  [64][68]   row-major, pre-scaled
//   K  [208][68]  row-major (rows >=197 zero)
//   S  [64][212]
//   VT [64][212]  d-major (cols >=197 zero)
//   inv[64]
// ---------------------------------------------------------------------------
#define NP_   208
#define KLD_  68
#define SLD_  212
#define Q_OFF 0
#define K_OFF (64 * KLD_)                  // 4352
#define S_OFF (K_OFF + NP_ * KLD_)         // 18496
#define V_OFF (S_OFF + 64 * SLD_)          // 32064
#define I_OFF (V_OFF + 64 * SLD_)          // 45632
#define ATTN_SMEM_WORDS (I_OFF + 64)       // 45696 words = 182784 B

__global__ void __launch_bounds__(256) attn_kernel(const float* __restrict__ scale)
{
    extern __shared__ float sm[];
    float* Q  = sm + Q_OFF;
    float* Kt = sm + K_OFF;
    float* S  = sm + S_OFF;
    float* VT = sm + V_OFF;
    float* inv = sm + I_OFF;

    const int tid = threadIdx.x;
    const int rb = blockIdx.x, h = blockIdx.y, b = blockIdx.z;
    const int base = b * N_;
    const int q0 = rb * 64;
    const int Nq = min(64, N_ - q0);
    const float sc = scale[h];

    const int warp = tid >> 5, lane = tid & 31;
    const int gp = lane >> 2, tg = lane & 3;

    // ---- stage Q (pre-scaled, zero-padded rows) ----
    for (int idx = tid; idx < 64 * 16; idx += 256) {
        int i = idx >> 4, d4 = (idx & 15) << 2;
        float4 v = make_float4(0.f, 0.f, 0.f, 0.f);
        if (i < Nq)
            v = *(const float4*)&g_qkv[(size_t)(base + q0 + i) * O3_ + h * HD_ + d4];
        v.x *= sc; v.y *= sc; v.z *= sc; v.w *= sc;
        *(float4*)&Q[i * KLD_ + d4] = v;
    }
    // ---- stage K (rows >= 197 zero) ----
    for (int idx = tid; idx < NP_ * 16; idx += 256) {
        int j = idx >> 4, d4 = (idx & 15) << 2;
        float4 v = make_float4(0.f, 0.f, 0.f, 0.f);
        if (j < N_)
            v = *(const float4*)&g_qkv[(size_t)(base + j) * O3_ + C_ + h * HD_ + d4];
        *(float4*)&Kt[j * KLD_ + d4] = v;
    }
    // ---- stage V transposed (cols >= 197 zero) ----
    for (int idx = tid; idx < NP_ * 16; idx += 256) {
        int j = idx >> 4, d4 = (idx & 15) << 2;
        float4 v = make_float4(0.f, 0.f, 0.f, 0.f);
        if (j < N_)
            v = *(const float4*)&g_qkv[(size_t)(base + j) * O3_ + 2 * C_ + h * HD_ + d4];
        VT[(d4 + 0) * SLD_ + j] = v.x;
        VT[(d4 + 1) * SLD_ + j] = v.y;
        VT[(d4 + 2) * SLD_ + j] = v.z;
        VT[(d4 + 3) * SLD_ + j] = v.w;
    }
    __syncthreads();

    // ---- S = Q K^T : warp tile m16 x n104 (4 m-groups x 2 n-halves) ----
    {
        const int wm = (warp & 3) * 16;
        const int wn = (warp >> 2) * 104;   // 13 n-tiles of 8
        float acc[13][4];
#pragma unroll
        for (int nt = 0; nt < 13; nt++)
#pragma unroll
            for (int k = 0; k < 4; k++) acc[nt][k] = 0.f;

#pragma unroll
        for (int kk = 0; kk < 8; kk++) {
            int k8 = kk * 8;
            uint32_t a[4];
            {
                const uint32_t* ap = (const uint32_t*)Q + (wm + gp) * KLD_ + k8 + tg;
                a[0] = ap[0];
                a[2] = ap[4];
                a[1] = ap[8 * KLD_];
                a[3] = ap[8 * KLD_ + 4];
            }
#pragma unroll
            for (int nt = 0; nt < 13; nt++) {
                const uint32_t* bp = (const uint32_t*)Kt + (wn + nt * 8 + gp) * KLD_ + k8 + tg;
                mma_m16n8k8(acc[nt], a, bp[0], bp[4]);
            }
        }
#pragma unroll
        for (int nt = 0; nt < 13; nt++) {
            int cc = wn + nt * 8 + 2 * tg;
            *(float2*)&S[(wm + gp) * SLD_ + cc]     = make_float2(acc[nt][0], acc[nt][1]);
            *(float2*)&S[(wm + gp + 8) * SLD_ + cc] = make_float2(acc[nt][2], acc[nt][3]);
        }
    }
    __syncthreads();

    // ---- softmax (4 threads/row); diag excluded inline; 1/sum deferred ----
    {
        int row = tid >> 2, sub = tid & 3;
        float* Sr = &S[row * SLD_];
        int diag = q0 + row;                 // may be >= N_ for padded rows
        float mx = -1e30f;
        for (int j = sub; j < N_; j += 4)
            if (j != diag) mx = fmaxf(mx, Sr[j]);
        mx = fmaxf(mx, __shfl_xor_sync(0xffffffffu, mx, 1));
        mx = fmaxf(mx, __shfl_xor_sync(0xffffffffu, mx, 2));
        float s = 0.f;
        for (int j = sub; j < N_; j += 4) {
            float e = (j == diag) ? 0.f : __expf(Sr[j] - mx);
            Sr[j] = e;
            s += e;
        }
        s += __shfl_xor_sync(0xffffffffu, s, 1);
        s += __shfl_xor_sync(0xffffffffu, s, 2);
        if (sub == 0) inv[row] = 1.0f / s;
        // note: S cols [197,208) remain exactly 0 (K pad) -> no PV contribution
    }
    __syncthreads();

    // ---- O = P V : warp tile m16 x n32, k=208 ----
    {
        const int wm = (warp & 3) * 16;
        const int wn = (warp >> 2) * 32;    // 4 n-tiles
        float acc[4][4];
#pragma unroll
        for (int nt = 0; nt < 4; nt++)
#pragma unroll
            for (int k = 0; k < 4; k++) acc[nt][k] = 0.f;

#pragma unroll 2
        for (int kk = 0; kk < NP_ / 8; kk++) {
            int k8 = kk * 8;
            uint32_t a[4];
            {
                const uint32_t* ap = (const uint32_t*)S + (wm + gp) * SLD_ + k8 + tg;
                a[0] = ap[0];
                a[2] = ap[4];
                a[1] = ap[8 * SLD_];
                a[3] = ap[8 * SLD_ + 4];
            }
#pragma unroll
            for (int nt = 0; nt < 4; nt++) {
                const uint32_t* bp = (const uint32_t*)VT + (wn + nt * 8 + gp) * SLD_ + k8 + tg;
                mma_m16n8k8(acc[nt], a, bp[0], bp[4]);
            }
        }
        // epilogue: *= 1/sum, write g_attn
#pragma unroll
        for (int nt = 0; nt < 4; nt++) {
            int cc = h * HD_ + wn + nt * 8 + 2 * tg;
            int r0 = wm + gp;
            if (r0 < Nq) {
                float iv = inv[r0];
                *(float2*)&g_attn[(size_t)(base + q0 + r0) * C_ + cc] =
                    make_float2(acc[nt][0] * iv, acc[nt][1] * iv);
            }
            if (r0 + 8 < Nq) {
                float iv = inv[r0 + 8];
                *(float2*)&g_attn[(size_t)(base + q0 + r0 + 8) * C_ + cc] =
                    make_float2(acc[nt][2] * iv, acc[nt][3] * iv);
            }
        }
    }
}

// ---------------------------------------------------------------------------
// launch
// ---------------------------------------------------------------------------
extern "C" void kernel_launch(void* const* d_in, const int* in_sizes, int n_in,
                              void* d_out, int out_size)
{
    const float* x      = (const float*)d_in[0];
    const float* scale  = (const float*)d_in[1];
    const float* w_qkv  = (const float*)d_in[2];
    const float* w_proj = (const float*)d_in[3];
    const float* b_proj = (const float*)d_in[4];
    float* out = (float*)d_out;

    float *qkv_p, *attn_p;
    cudaGetSymbolAddress((void**)&qkv_p, g_qkv);
    cudaGetSymbolAddress((void**)&attn_p, g_attn);

    const int smem_gemm = 2 * 2 * 128 * 36 * 4;        // 73728 B
    const int smem_attn = ATTN_SMEM_WORDS * 4;         // 182784 B
    cudaFuncSetAttribute(gemm_tf32<false>, cudaFuncAttributeMaxDynamicSharedMemorySize, smem_gemm);
    cudaFuncSetAttribute(gemm_tf32<true>,  cudaFuncAttributeMaxDynamicSharedMemorySize, smem_gemm);
    cudaFuncSetAttribute(attn_kernel,      cudaFuncAttributeMaxDynamicSharedMemorySize, smem_attn);

    // 1) QKV projection: [12608, 2304]
    gemm_tf32<false><<<dim3(O3_ / 128, (M_ + 127) / 128), 256, smem_gemm>>>(
        x, w_qkv, qkv_p, M_, O3_, C_, nullptr, nullptr);

    // 2) fused masked attention per (row-block, head, batch)
    attn_kernel<<<dim3(4, H_, B_), 256, smem_attn>>>(scale);

    // 3) output projection + bias + residual
    gemm_tf32<true><<<dim3(C_ / 128, (M_ + 127) / 128), 256, smem_gemm>>>(
        attn_p, w_proj, out, M_, C_, C_, b_proj, x);
}

// round 9
// speedup vs baseline: 1.7510x; 1.5021x over previous
#include <cuda_runtime.h>
#include <stdint.h>

// Problem constants
#define B_   64
#define N_   197
#define C_   768
#define H_   12
#define HD_  64
#define M_   (B_ * N_)     // 12608 rows
#define O3_  (3 * C_)      // 2304 qkv output dim

// Scratch (device globals: allocation-free rule)
__device__ float g_qkv[M_ * O3_];    // [12608, 2304]
__device__ float g_attn[M_ * C_];    // [12608, 768]

// ---------------------------------------------------------------------------
// helpers
// ---------------------------------------------------------------------------
__device__ __forceinline__ void mma_m16n8k8(float c[4], const uint32_t a[4],
                                            uint32_t b0, uint32_t b1) {
    asm volatile(
        "mma.sync.aligned.m16n8k8.row.col.f32.tf32.tf32.f32 "
        "{%0,%1,%2,%3}, {%4,%5,%6,%7}, {%8,%9}, {%0,%1,%2,%3};"
        : "+f"(c[0]), "+f"(c[1]), "+f"(c[2]), "+f"(c[3])
        : "r"(a[0]), "r"(a[1]), "r"(a[2]), "r"(a[3]), "r"(b0), "r"(b1));
}

__device__ __forceinline__ void cp_async16(uint32_t s, const void* g, int srcsz) {
    asm volatile("cp.async.cg.shared.global [%0], [%1], 16, %2;"
                 :: "r"(s), "l"(g), "r"(srcsz));
}
#define CP_COMMIT() asm volatile("cp.async.commit_group;")

// ---------------------------------------------------------------------------
// TF32 GEMM: C[m][n] = sum_k A[m][k] * W[n][k]  (+ bias[n] + resid[m][n])
// A row-major [M,K], W row-major [N,K]. CTA tile 128x128, BK=32, 256 threads.
// cp.async double-buffered; ONE barrier per k-tile (issue-after-sync order
// makes the write target safe: buffer (kt+1)&1 was last read in kt-1, which
// the barrier at iteration kt already fenced). 2 CTAs/SM forced.
// ---------------------------------------------------------------------------
template <bool EPI>
__global__ void __launch_bounds__(256, 2) gemm_tf32(
    const float* __restrict__ A, const float* __restrict__ W,
    float* __restrict__ C, int M, int N, int K,
    const float* __restrict__ bias, const float* __restrict__ resid)
{
    extern __shared__ float smem[];
    const int LDT = 36;              // 32 + 4 pad -> conflict-free frag loads
    const int TILE_W = 128 * LDT;    // words per buffer

    const int tid  = threadIdx.x;
    const int m0   = blockIdx.y * 128;
    const int n0   = blockIdx.x * 128;
    const int warp = tid >> 5, lane = tid & 31;
    const int wm   = (warp & 3) * 32;
    const int wn   = (warp >> 2) * 64;
    const int gp   = lane >> 2, tg = lane & 3;

    const uint32_t smem_u32 = (uint32_t)__cvta_generic_to_shared(smem);

    // per-thread staging descriptors (4 float4 per matrix per tile)
    const float* Ag[4];
    const float* Wg[4];
    int          av[4];
    uint32_t     sa[4], sb[4];
#pragma unroll
    for (int it = 0; it < 4; it++) {
        int f4 = it * 256 + tid;
        int row = f4 >> 3, c4 = (f4 & 7) << 2;
        int gra = m0 + row;
        av[it] = (gra < M) ? 16 : 0;
        Ag[it] = A + (size_t)(gra < M ? gra : 0) * K + c4;
        Wg[it] = W + (size_t)(n0 + row) * K + c4;
        sa[it] = smem_u32 + (uint32_t)(row * LDT + c4) * 4u;
        sb[it] = smem_u32 + (uint32_t)(2 * TILE_W + row * LDT + c4) * 4u;
    }

    float acc[2][8][4];
#pragma unroll
    for (int i = 0; i < 2; i++)
#pragma unroll
        for (int j = 0; j < 8; j++)
#pragma unroll
            for (int k = 0; k < 4; k++) acc[i][j][k] = 0.f;

    const int KT = K >> 5;

    // prologue: tile 0 -> buffer 0
#pragma unroll
    for (int it = 0; it < 4; it++) {
        cp_async16(sa[it], Ag[it], av[it]);
        cp_async16(sb[it], Wg[it], 16);
    }
    CP_COMMIT();

    for (int kt = 0; kt < KT; kt++) {
        asm volatile("cp.async.wait_group 0;");   // tile kt landed
        __syncthreads();                           // visible to all; kt-1 reads done

        if (kt + 1 < KT) {                        // overlap: load kt+1 during compute kt
            int kb = (kt + 1) << 5;
            uint32_t boff = (uint32_t)(((kt + 1) & 1) * TILE_W) * 4u;
#pragma unroll
            for (int it = 0; it < 4; it++) {
                cp_async16(sa[it] + boff, Ag[it] + kb, av[it]);
                cp_async16(sb[it] + boff, Wg[it] + kb, 16);
            }
            CP_COMMIT();
        }

        const uint32_t* Ab = (const uint32_t*)smem + (kt & 1) * TILE_W;
        const uint32_t* Bb = (const uint32_t*)smem + 2 * TILE_W + (kt & 1) * TILE_W;
#pragma unroll
        for (int kk = 0; kk < 4; kk++) {
            int k8 = kk * 8;
            uint32_t af[2][4];
#pragma unroll
            for (int mt = 0; mt < 2; mt++) {
                const uint32_t* ap = Ab + (wm + mt * 16 + gp) * LDT + k8 + tg;
                af[mt][0] = ap[0];
                af[mt][2] = ap[4];
                af[mt][1] = ap[8 * LDT];
                af[mt][3] = ap[8 * LDT + 4];
            }
#pragma unroll
            for (int nt = 0; nt < 8; nt++) {
                const uint32_t* bp = Bb + (wn + nt * 8 + gp) * LDT + k8 + tg;
                uint32_t b0 = bp[0], b1 = bp[4];
                mma_m16n8k8(acc[0][nt], af[0], b0, b1);
                mma_m16n8k8(acc[1][nt], af[1], b0, b1);
            }
        }
    }

    // ---- epilogue ----
#pragma unroll
    for (int mt = 0; mt < 2; mt++) {
#pragma unroll
        for (int nt = 0; nt < 8; nt++) {
            int r0 = m0 + wm + mt * 16 + gp;
            int cc = n0 + wn + nt * 8 + tg * 2;
            if (r0 < M) {
                float2 v = make_float2(acc[mt][nt][0], acc[mt][nt][1]);
                if (EPI) {
                    v.x += bias[cc]     + resid[(size_t)r0 * N + cc];
                    v.y += bias[cc + 1] + resid[(size_t)r0 * N + cc + 1];
                }
                *(float2*)(C + (size_t)r0 * N + cc) = v;
            }
            if (r0 + 8 < M) {
                float2 v = make_float2(acc[mt][nt][2], acc[mt][nt][3]);
                if (EPI) {
                    v.x += bias[cc]     + resid[(size_t)(r0 + 8) * N + cc];
                    v.y += bias[cc + 1] + resid[(size_t)(r0 + 8) * N + cc + 1];
                }
                *(float2*)(C + (size_t)(r0 + 8) * N + cc) = v;
            }
        }
    }
}

// ---------------------------------------------------------------------------
// Fused attention with tf32 MMA. One CTA per (b, h, 64-query block).
// 512 threads (16 warps). Q/K staged RAW via cp.async (zero-fill pads);
// scale[h] folded into softmax. V^T staged manually (needs transpose).
//   Q  [64][68]   row-major (raw)
//   K  [208][68]  row-major (rows >=197 zero)
//   S  [64][212]
//   VT [64][212]  d-major (cols >=197 zero)
//   inv[64]
// ---------------------------------------------------------------------------
#define NP_   208
#define NT_S  26                           // 208/8 n-tiles for S
#define KLD_  68
#define SLD_  212
#define Q_OFF 0
#define K_OFF (64 * KLD_)                  // 4352
#define S_OFF (K_OFF + NP_ * KLD_)         // 18496
#define V_OFF (S_OFF + 64 * SLD_)          // 32064
#define I_OFF (V_OFF + 64 * SLD_)          // 45632
#define ATTN_SMEM_WORDS (I_OFF + 64)       // 45696 words = 182784 B

__global__ void __launch_bounds__(512) attn_kernel(const float* __restrict__ scale)
{
    extern __shared__ float sm[];
    float* Q  = sm + Q_OFF;
    float* Kt = sm + K_OFF;
    float* S  = sm + S_OFF;
    float* VT = sm + V_OFF;
    float* inv = sm + I_OFF;

    const int tid = threadIdx.x;
    const int rb = blockIdx.x, h = blockIdx.y, b = blockIdx.z;
    const int base = b * N_;
    const int q0 = rb * 64;
    const int Nq = min(64, N_ - q0);
    const float sc = scale[h];

    const int warp = tid >> 5, lane = tid & 31;
    const int gp = lane >> 2, tg = lane & 3;
    const int mg = warp & 3, ng = warp >> 2;   // 4x4 warp grid

    const uint32_t smem_u32 = (uint32_t)__cvta_generic_to_shared(sm);

    // ---- async stage Q (raw) and K; zero-fill padded rows ----
    for (int idx = tid; idx < 64 * 16; idx += 512) {
        int i = idx >> 4, d4 = (idx & 15) << 2;
        const float* src = &g_qkv[(size_t)(base + q0 + (i < Nq ? i : 0)) * O3_ + h * HD_ + d4];
        cp_async16(smem_u32 + (uint32_t)(Q_OFF + i * KLD_ + d4) * 4u, src, i < Nq ? 16 : 0);
    }
    for (int idx = tid; idx < NP_ * 16; idx += 512) {
        int j = idx >> 4, d4 = (idx & 15) << 2;
        const float* src = &g_qkv[(size_t)(base + (j < N_ ? j : 0)) * O3_ + C_ + h * HD_ + d4];
        cp_async16(smem_u32 + (uint32_t)(K_OFF + j * KLD_ + d4) * 4u, src, j < N_ ? 16 : 0);
    }
    CP_COMMIT();

    // ---- stage V transposed (manual; overlaps with async above) ----
    for (int idx = tid; idx < NP_ * 16; idx += 512) {
        int j = idx >> 4, d4 = (idx & 15) << 2;
        float4 v = make_float4(0.f, 0.f, 0.f, 0.f);
        if (j < N_)
            v = *(const float4*)&g_qkv[(size_t)(base + j) * O3_ + 2 * C_ + h * HD_ + d4];
        VT[(d4 + 0) * SLD_ + j] = v.x;
        VT[(d4 + 1) * SLD_ + j] = v.y;
        VT[(d4 + 2) * SLD_ + j] = v.z;
        VT[(d4 + 3) * SLD_ + j] = v.w;
    }
    asm volatile("cp.async.wait_group 0;");
    __syncthreads();

    // ---- S = Q K^T : 16 warps, 4 m-groups x 4 n-groups, tiles round-robin ----
    {
        const int wm = mg * 16;
        float acc[7][4];
#pragma unroll
        for (int i = 0; i < 7; i++)
#pragma unroll
            for (int k = 0; k < 4; k++) acc[i][k] = 0.f;

#pragma unroll
        for (int kk = 0; kk < 8; kk++) {
            int k8 = kk * 8;
            uint32_t a[4];
            {
                const uint32_t* ap = (const uint32_t*)Q + (wm + gp) * KLD_ + k8 + tg;
                a[0] = ap[0];
                a[2] = ap[4];
                a[1] = ap[8 * KLD_];
                a[3] = ap[8 * KLD_ + 4];
            }
#pragma unroll
            for (int i = 0; i < 7; i++) {
                int t = ng + 4 * i;
                if (t < NT_S) {
                    const uint32_t* bp = (const uint32_t*)Kt + (t * 8 + gp) * KLD_ + k8 + tg;
                    mma_m16n8k8(acc[i], a, bp[0], bp[4]);
                }
            }
        }
#pragma unroll
        for (int i = 0; i < 7; i++) {
            int t = ng + 4 * i;
            if (t < NT_S) {
                int cc = t * 8 + 2 * tg;
                *(float2*)&S[(wm + gp) * SLD_ + cc]     = make_float2(acc[i][0], acc[i][1]);
                *(float2*)&S[(wm + gp + 8) * SLD_ + cc] = make_float2(acc[i][2], acc[i][3]);
            }
        }
    }
    __syncthreads();

    // ---- softmax (8 threads/row); scale folded; diag excluded; 1/sum deferred
    {
        int row = tid >> 3, sub = tid & 7;
        float* Sr = &S[row * SLD_];
        int diag = q0 + row;                 // may be >= N_ for padded rows
        float mx = -1e30f;
        for (int j = sub; j < N_; j += 8)
            if (j != diag) mx = fmaxf(mx, sc * Sr[j]);
        mx = fmaxf(mx, __shfl_xor_sync(0xffffffffu, mx, 1));
        mx = fmaxf(mx, __shfl_xor_sync(0xffffffffu, mx, 2));
        mx = fmaxf(mx, __shfl_xor_sync(0xffffffffu, mx, 4));
        float s = 0.f;
        for (int j = sub; j < N_; j += 8) {
            float e = (j == diag) ? 0.f : __expf(sc * Sr[j] - mx);
            Sr[j] = e;
            s += e;
        }
        s += __shfl_xor_sync(0xffffffffu, s, 1);
        s += __shfl_xor_sync(0xffffffffu, s, 2);
        s += __shfl_xor_sync(0xffffffffu, s, 4);
        if (sub == 0) inv[row] = 1.0f / s;
        // S cols [197,208) stay exactly 0 (K pad rows were zero) -> no PV term
    }
    __syncthreads();

    // ---- O = P V : 16 warps, each m16 x n16, k=208 ----
    {
        const int wm = mg * 16;
        const int wn = ng * 16;              // 2 n-tiles of 8
        float acc[2][4];
#pragma unroll
        for (int nt = 0; nt < 2; nt++)
#pragma unroll
            for (int k = 0; k < 4; k++) acc[nt][k] = 0.f;

#pragma unroll 2
        for (int kk = 0; kk < NP_ / 8; kk++) {
            int k8 = kk * 8;
            uint32_t a[4];
            {
                const uint32_t* ap = (const uint32_t*)S + (wm + gp) * SLD_ + k8 + tg;
                a[0] = ap[0];
                a[2] = ap[4];
                a[1] = ap[8 * SLD_];
                a[3] = ap[8 * SLD_ + 4];
            }
#pragma unroll
            for (int nt = 0; nt < 2; nt++) {
                const uint32_t* bp = (const uint32_t*)VT + (wn + nt * 8 + gp) * SLD_ + k8 + tg;
                mma_m16n8k8(acc[nt], a, bp[0], bp[4]);
            }
        }
        // epilogue: *= 1/sum, write g_attn
#pragma unroll
        for (int nt = 0; nt < 2; nt++) {
            int cc = h * HD_ + wn + nt * 8 + 2 * tg;
            int r0 = wm + gp;
            if (r0 < Nq) {
                float iv = inv[r0];
                *(float2*)&g_attn[(size_t)(base + q0 + r0) * C_ + cc] =
                    make_float2(acc[nt][0] * iv, acc[nt][1] * iv);
            }
            if (r0 + 8 < Nq) {
                float iv = inv[r0 + 8];
                *(float2*)&g_attn[(size_t)(base + q0 + r0 + 8) * C_ + cc] =
                    make_float2(acc[nt][2] * iv, acc[nt][3] * iv);
            }
        }
    }
}

// ---------------------------------------------------------------------------
// launch
// ---------------------------------------------------------------------------
extern "C" void kernel_launch(void* const* d_in, const int* in_sizes, int n_in,
                              void* d_out, int out_size)
{
    const float* x      = (const float*)d_in[0];
    const float* scale  = (const float*)d_in[1];
    const float* w_qkv  = (const float*)d_in[2];
    const float* w_proj = (const float*)d_in[3];
    const float* b_proj = (const float*)d_in[4];
    float* out = (float*)d_out;

    float *qkv_p, *attn_p;
    cudaGetSymbolAddress((void**)&qkv_p, g_qkv);
    cudaGetSymbolAddress((void**)&attn_p, g_attn);

    const int smem_gemm = 2 * 2 * 128 * 36 * 4;        // 73728 B
    const int smem_attn = ATTN_SMEM_WORDS * 4;         // 182784 B
    cudaFuncSetAttribute(gemm_tf32<false>, cudaFuncAttributeMaxDynamicSharedMemorySize, smem_gemm);
    cudaFuncSetAttribute(gemm_tf32<true>,  cudaFuncAttributeMaxDynamicSharedMemorySize, smem_gemm);
    cudaFuncSetAttribute(attn_kernel,      cudaFuncAttributeMaxDynamicSharedMemorySize, smem_attn);

    // 1) QKV projection: [12608, 2304]
    gemm_tf32<false><<<dim3(O3_ / 128, (M_ + 127) / 128), 256, smem_gemm>>>(
        x, w_qkv, qkv_p, M_, O3_, C_, nullptr, nullptr);

    // 2) fused masked attention per (row-block, head, batch)
    attn_kernel<<<dim3(4, H_, B_), 512, smem_attn>>>(scale);

    // 3) output projection + bias + residual
    gemm_tf32<true><<<dim3(C_ / 128, (M_ + 127) / 128), 256, smem_gemm>>>(
        attn_p, w_proj, out, M_, C_, C_, b_proj, x);
}